// round 12
// baseline (speedup 1.0000x reference)
#include <cuda_runtime.h>
#include <cuda_bf16.h>
#include <math.h>
#include <stdint.h>

// ---------------- problem constants ----------------
#define BATCH 8
#define TSTEPS 16
#define CIN0 192
#define HC0 64
#define HC1 32
#define HC2 64
#define IMG_H 28
#define IMG_W 28
#define HW 784

// ---------------- device scratch (no allocs allowed) ----------------
__device__ float g_gx0[(size_t)BATCH * TSTEPS * 4 * HC0 * HW];

#define SZ0 (BATCH * HC0 * HW)
#define SZ1 (BATCH * HC1 * HW)
#define SZ2 (BATCH * HC2 * HW)
#define OFF_H0A 0
#define OFF_H0B (OFF_H0A + SZ0)
#define OFF_C0  (OFF_H0B + SZ0)
#define OFF_H1A (OFF_C0  + SZ0)
#define OFF_H1B (OFF_H1A + SZ1)
#define OFF_C1  (OFF_H1B + SZ1)
#define OFF_H2A (OFF_C1  + SZ1)
#define OFF_H2B (OFF_H2A + SZ2)
#define OFF_C2  (OFF_H2B + SZ2)
#define NSTATE  (OFF_C2  + SZ2)
__device__ float g_state[NSTATE];

// pre-transposed tf32 weight buffers, layout [y][chunk][tap][m(32)][ci(8)]
// oc(m) = (m>>3)*HC + y*8 + (m&7)          (R5 layout)
#define WPC 2304
#define WOFF_GX0 0
#define WSZ_GX0 (8 * 24 * WPC)
#define WOFF_L0 (WOFF_GX0 + WSZ_GX0)
#define WSZ_L0  (8 * 8 * WPC)
#define WOFF_L1 (WOFF_L0 + WSZ_L0)
#define WSZ_L1  (4 * 12 * WPC)
#define WOFF_L2 (WOFF_L1 + WSZ_L1)
#define WSZ_L2  (8 * 12 * WPC)
#define WTOTAL  (WOFF_L2 + WSZ_L2)
__device__ uint32_t g_wt[WTOTAL];

__global__ void init_zero_kernel(float* p, int n) {
    int i = blockIdx.x * blockDim.x + threadIdx.x;
    if (i < n) p[i] = 0.f;
}

// ---------------- tf32 helpers ----------------
__device__ __forceinline__ uint32_t f2tf32(float f) {
    uint32_t u;
    asm("cvt.rna.tf32.f32 %0, %1;" : "=r"(u) : "f"(f));
    return u;
}

__device__ __forceinline__ void mma_tf32(float c[4],
                                         uint32_t a0, uint32_t a1, uint32_t a2, uint32_t a3,
                                         uint32_t b0, uint32_t b1) {
    asm volatile(
        "mma.sync.aligned.m16n8k8.row.col.f32.tf32.tf32.f32 "
        "{%0,%1,%2,%3}, {%4,%5,%6,%7}, {%8,%9}, {%0,%1,%2,%3};"
        : "+f"(c[0]), "+f"(c[1]), "+f"(c[2]), "+f"(c[3])
        : "r"(a0), "r"(a1), "r"(a2), "r"(a3), "r"(b0), "r"(b1));
}

__device__ __forceinline__ float sigmoidf_(float x) {
    return 1.0f / (1.0f + __expf(-x));
}

// ---------------- weight prep: transpose + tf32 (R5 layout) ----------------
__global__ void prep_weights(const float* __restrict__ WA, int cinA,
                             const float* __restrict__ WB, int cinB,
                             int HC, int chunks, uint32_t* __restrict__ dst, int total)
{
    int idx = blockIdx.x * blockDim.x + threadIdx.x;
    if (idx >= total) return;
    int ci  = idx & 7;
    int m   = (idx >> 3) & 31;
    int tap = (idx >> 8) % 9;
    int chy = idx / WPC;
    int ch  = chy % chunks;
    int y   = chy / chunks;
    int oc  = (m >> 3) * HC + y * 8 + (m & 7);
    int cg  = ch * 8 + ci;
    float w;
    if (cg < cinA) w = WA[((size_t)oc * cinA + cg) * 9 + tap];
    else           w = WB[((size_t)oc * cinB + (cg - cinA)) * 9 + tap];
    dst[idx] = f2tf32(w);
}

// ---------------- conv 3x3 + fused LSTM body (R5 engine, unchanged) ----------
#define SIN_STR 200

struct SmemU {
    union {
        struct {
            uint32_t in[2][8 * SIN_STR];
            uint32_t w[2][WPC];
        } mm;
        float gates[4 * 8 * 112];
    };
};

__device__ __forceinline__ void conv_cell_body(
    SmemU& sm,
    int n, int yb, int rowbase,
    const float* __restrict__ inA, int cinA, size_t inAStride,
    const float* __restrict__ inB, int cinB,
    const uint32_t* __restrict__ wt,
    const float* __restrict__ bias,
    const float* __restrict__ pre, size_t preStride,
    int HC,
    float* __restrict__ out, size_t outStride,   // plain path (hout == nullptr)
    const float* __restrict__ Wp,
    float* __restrict__ hout, float* __restrict__ c,
    float* __restrict__ yout, int t)
{
    const int hcb = yb * 8;

    const int tid    = threadIdx.x;
    const int lane   = tid & 31;
    const int wid    = tid >> 5;
    const int warp_m = wid & 1;
    const int warp_n = wid >> 1;
    const int g      = lane >> 2;
    const int ctg    = lane & 3;

    const int chunks = (cinA + cinB) >> 3;

    int off[7];
#pragma unroll
    for (int s = 0; s < 7; ++s) {
        int nl = warp_n * 56 + s * 8 + g;
        int r = nl / 28;
        off[s] = r * 30 + (nl - r * 28);
    }

    float acc[7][4];
#pragma unroll
    for (int s = 0; s < 7; ++s)
#pragma unroll
        for (int j = 0; j < 4; ++j) acc[s][j] = 0.f;

    float rin[12];
    uint4 rw4[5];

    auto load_chunk = [&](int ch) {
        const int cstart = ch * 8;
        const float* src = (cstart < cinA)
            ? inA + (size_t)n * inAStride + (size_t)cstart * HW
            : inB + ((size_t)n * cinB + (cstart - cinA)) * HW;
#pragma unroll
        for (int k = 0; k < 12; ++k) {
            int idx = tid + k * 128;
            float v = 0.f;
            if (idx < 1440) {
                int ci  = idx / 180;
                int rem = idx - ci * 180;
                int pr  = rem / 30;
                int gr  = rowbase + pr - 1;
                int gc  = (rem - pr * 30) - 1;
                if (gr >= 0 && gr < IMG_H && gc >= 0 && gc < IMG_W)
                    v = src[(size_t)ci * HW + gr * IMG_W + gc];
            }
            rin[k] = v;
        }
        const uint4* wsrc = (const uint4*)(wt + ((size_t)yb * chunks + ch) * WPC);
#pragma unroll
        for (int k = 0; k < 5; ++k) {
            int i4 = tid + k * 128;
            if (i4 < 576) rw4[k] = wsrc[i4];
        }
    };

    load_chunk(0);

    for (int ch = 0; ch < chunks; ++ch) {
        const int st = ch & 1;
#pragma unroll
        for (int k = 0; k < 12; ++k) {
            int idx = tid + k * 128;
            if (idx < 1440) {
                int ci  = idx / 180;
                int rem = idx - ci * 180;
                sm.mm.in[st][ci * SIN_STR + rem] = f2tf32(rin[k]);
            }
        }
#pragma unroll
        for (int k = 0; k < 5; ++k) {
            int i4 = tid + k * 128;
            if (i4 < 576) ((uint4*)sm.mm.w[st])[i4] = rw4[k];
        }
        __syncthreads();

        if (ch + 1 < chunks) load_chunk(ch + 1);

        const uint32_t* win = sm.mm.in[st];
        const uint32_t* ww  = sm.mm.w[st];
#pragma unroll
        for (int kr = 0; kr < 3; ++kr) {
#pragma unroll
            for (int kc = 0; kc < 3; ++kc) {
                const int tap = kr * 3 + kc;
                const uint32_t* wp = ww + tap * 256 + (warp_m * 16 + g) * 8 + ctg;
                uint32_t a0 = wp[0];
                uint32_t a1 = wp[64];
                uint32_t a2 = wp[4];
                uint32_t a3 = wp[68];
                const int bbase = ctg * SIN_STR + kr * 30 + kc;
#pragma unroll
                for (int s = 0; s < 7; ++s) {
                    uint32_t b0 = win[bbase + off[s]];
                    uint32_t b1 = win[bbase + off[s] + 4 * SIN_STR];
                    mma_tf32(acc[s], a0, a1, a2, a3, b0, b1);
                }
            }
        }
    }

    // ---- epilogue ----
    const int m0  = warp_m * 16 + g;
    const int oc0 = (m0 >> 3) * HC + hcb + (m0 & 7);
    const int m1  = m0 + 8;
    const int oc1 = (m1 >> 3) * HC + hcb + (m1 & 7);
    float bv0 = 0.f, bv1 = 0.f;
    if (bias) { bv0 = bias[oc0]; bv1 = bias[oc1]; }

    if (hout == nullptr) {
#pragma unroll
        for (int s = 0; s < 7; ++s) {
#pragma unroll
            for (int j = 0; j < 2; ++j) {
                int nl = warp_n * 56 + s * 8 + 2 * ctg + j;
                int r = nl / 28;
                int px = (rowbase + r) * IMG_W + (nl - r * 28);
                float v0 = acc[s][j]     + bv0;
                float v1 = acc[s][2 + j] + bv1;
                if (pre) {
                    v0 += pre[(size_t)n * preStride + (size_t)oc0 * HW + px];
                    v1 += pre[(size_t)n * preStride + (size_t)oc1 * HW + px];
                }
                out[(size_t)n * outStride + (size_t)oc0 * HW + px] = v0;
                out[(size_t)n * outStride + (size_t)oc1 * HW + px] = v1;
            }
        }
        return;
    }

    __syncthreads();
#pragma unroll
    for (int s = 0; s < 7; ++s) {
#pragma unroll
        for (int j = 0; j < 2; ++j) {
            int nl = warp_n * 56 + s * 8 + 2 * ctg + j;
            float v0 = acc[s][j]     + bv0;
            float v1 = acc[s][2 + j] + bv1;
            if (pre) {
                int r = nl / 28;
                int px = (rowbase + r) * IMG_W + (nl - r * 28);
                v0 += pre[(size_t)n * preStride + (size_t)oc0 * HW + px];
                v1 += pre[(size_t)n * preStride + (size_t)oc1 * HW + px];
            }
            sm.gates[((m0 >> 3) * 8 + (m0 & 7)) * 112 + nl] = v0;
            sm.gates[((m1 >> 3) * 8 + (m1 & 7)) * 112 + nl] = v1;
        }
    }
    __syncthreads();

#pragma unroll
    for (int k = 0; k < 7; ++k) {
        int e   = tid + k * 128;
        int hcl = e / 112;
        int nl  = e - hcl * 112;
        int r   = nl / 28;
        int px  = (rowbase + r) * IMG_W + (nl - r * 28);
        int hc  = hcb + hcl;

        float g0 = sm.gates[(0 * 8 + hcl) * 112 + nl];
        float g1 = sm.gates[(1 * 8 + hcl) * 112 + nl];
        float g2 = sm.gates[(2 * 8 + hcl) * 112 + nl];
        float g3 = sm.gates[(3 * 8 + hcl) * 112 + nl];

        size_t sidx = ((size_t)n * HC + hc) * HW + px;
        float cv = c[sidx];
        float pi = Wp[(size_t)(0 * HC + hc) * HW + px];
        float pf = Wp[(size_t)(1 * HC + hc) * HW + px];
        float po = Wp[(size_t)(2 * HC + hc) * HW + px];

        float gi = sigmoidf_(g0 + cv * pi);
        float gf = sigmoidf_(g1 + cv * pf);
        float cc = gf * cv + gi * tanhf(g2);
        float go = sigmoidf_(g3 + cc * po);
        float hv = go * tanhf(cc);

        c[sidx] = cc;
        hout[sidx] = hv;
        if (yout)
            yout[(((size_t)n * TSTEPS + t) * HC + hc) * HW + px] = hv;
    }
}

// ---------------- standalone conv kernel (gx0 batched, L1(t), L2(15)) -------
__global__ void __launch_bounds__(128, 4) conv3x3_cell(
    const float* __restrict__ inA, int cinA, size_t inAStride,
    const float* __restrict__ inB, int cinB,
    const uint32_t* __restrict__ wt,
    const float* __restrict__ bias,
    const float* __restrict__ pre, size_t preStride,
    int HC,
    float* __restrict__ out, size_t outStride,
    const float* __restrict__ Wp,
    float* __restrict__ hout, float* __restrict__ c,
    float* __restrict__ yout, int t)
{
    __shared__ SmemU sm;
    conv_cell_body(sm, blockIdx.x, blockIdx.y, blockIdx.z * 4,
                   inA, cinA, inAStride, inB, cinB, wt, bias, pre, preStride,
                   HC, out, outStride, Wp, hout, c, yout, t);
}

// ---------------- combo kernel: L0(t) | L2(t-1), balanced 448+448 ----------
#define GX0_FRAME ((size_t)4 * HC0 * HW)
#define GX0_BSTR  ((size_t)TSTEPS * 4 * HC0 * HW)

__global__ void __launch_bounds__(128, 4) combo_kernel(
    int t,
    float* __restrict__ gx0,
    float* __restrict__ state,
    const uint32_t* __restrict__ wt,
    const float* __restrict__ bx2,
    const float* __restrict__ Wp0, const float* __restrict__ Wp2,
    float* __restrict__ y)
{
    __shared__ SmemU sm;

    float* h0buf[2] = { state + OFF_H0A, state + OFF_H0B };
    float* h1buf[2] = { state + OFF_H1A, state + OFF_H1B };
    float* h2buf[2] = { state + OFF_H2A, state + OFF_H2B };

    const int b = blockIdx.x;

    if (b < 448) {
        // ---- L0 at t ----
        int local = b;
        int z = local % 7; local /= 7;
        int yb = local % 8;
        int n  = local / 8;
        const int rb = t & 1, wb = rb ^ 1;
        conv_cell_body(sm, n, yb, z * 4,
                       h0buf[rb], HC0, (size_t)HC0 * HW, nullptr, 0,
                       wt + WOFF_L0, nullptr,
                       gx0 + (size_t)t * GX0_FRAME, GX0_BSTR,
                       HC0, nullptr, 0,
                       Wp0, h0buf[wb], state + OFF_C0, nullptr, t);
    } else {
        // ---- L2 at t2 = t - 1 ----
        const int t2 = t - 1;
        if (t2 < 0) return;
        int local = b - 448;
        int z = local % 7; local /= 7;
        int yb = local % 8;
        int n  = local / 8;
        const int rb = t2 & 1, wb = rb ^ 1;
        conv_cell_body(sm, n, yb, z * 4,
                       h1buf[wb], HC1, (size_t)HC1 * HW,   // h1(t2), written by L1(t2)
                       h2buf[rb], HC2,
                       wt + WOFF_L2, bx2, nullptr, 0,
                       HC2, nullptr, 0,
                       Wp2, h2buf[wb], state + OFF_C2, y, t2);
    }
}

// ---------------- host launch ----------------
extern "C" void kernel_launch(void* const* d_in, const int* in_sizes, int n_in,
                              void* d_out, int out_size)
{
    const float* x   = (const float*)d_in[0];
    const float* Wx0 = (const float*)d_in[1];
    const float* bx0 = (const float*)d_in[2];
    const float* Wh0 = (const float*)d_in[3];
    const float* Wp0 = (const float*)d_in[4];
    const float* Wx1 = (const float*)d_in[5];
    const float* bx1 = (const float*)d_in[6];
    const float* Wh1 = (const float*)d_in[7];
    const float* Wp1 = (const float*)d_in[8];
    const float* Wx2 = (const float*)d_in[9];
    const float* bx2 = (const float*)d_in[10];
    const float* Wh2 = (const float*)d_in[11];
    const float* Wp2 = (const float*)d_in[12];
    float* y = (float*)d_out;

    float *gx0, *state;
    uint32_t* wt;
    cudaGetSymbolAddress((void**)&gx0,   g_gx0);
    cudaGetSymbolAddress((void**)&state, g_state);
    cudaGetSymbolAddress((void**)&wt,    g_wt);

    float* h0buf[2] = { state + OFF_H0A, state + OFF_H0B };
    float* h1buf[2] = { state + OFF_H1A, state + OFF_H1B };
    float* h2buf[2] = { state + OFF_H2A, state + OFF_H2B };
    float* c1 = state + OFF_C1;
    float* c2 = state + OFF_C2;

    init_zero_kernel<<<(NSTATE + 255) / 256, 256>>>(state, NSTATE);

    prep_weights<<<(WSZ_GX0 + 255) / 256, 256>>>(Wx0, CIN0, nullptr, 0, HC0, 24, wt + WOFF_GX0, WSZ_GX0);
    prep_weights<<<(WSZ_L0  + 255) / 256, 256>>>(Wh0, HC0,  nullptr, 0, HC0,  8, wt + WOFF_L0,  WSZ_L0);
    prep_weights<<<(WSZ_L1  + 255) / 256, 256>>>(Wx1, HC0,  Wh1, HC1, HC1, 12, wt + WOFF_L1,  WSZ_L1);
    prep_weights<<<(WSZ_L2  + 255) / 256, 256>>>(Wx2, HC1,  Wh2, HC2, HC2, 12, wt + WOFF_L2,  WSZ_L2);

    // batched gx0 = conv(x, Wx0) + bx0 over all B*T frames (plain path)
    conv3x3_cell<<<dim3(BATCH * TSTEPS, HC0 / 8, 7), 128>>>(
        x, CIN0, (size_t)CIN0 * HW, nullptr, 0, wt + WOFF_GX0, bx0, nullptr, 0,
        HC0, gx0, GX0_FRAME, nullptr, nullptr, nullptr, nullptr, 0);

    for (int t = 0; t < TSTEPS; ++t) {
        const int rb = t & 1;
        const int wb = rb ^ 1;

        // launch A: L0(t) || L2(t-1)   (896 balanced R5 blocks)
        combo_kernel<<<896, 128>>>(t, gx0, state, wt, bx2, Wp0, Wp2, y);

        // launch B: L1(t) = conv(h0_new, Wx1) + conv(h1_old, Wh1) + bx1; fused
        conv3x3_cell<<<dim3(BATCH, HC1 / 8, 7), 128>>>(
            h0buf[wb], HC0, (size_t)HC0 * HW, h1buf[rb], HC1, wt + WOFF_L1, bx1, nullptr, 0,
            HC1, nullptr, 0, Wp1, h1buf[wb], c1, nullptr, t);
    }

    // epilogue: L2(15)
    {
        const int t2 = TSTEPS - 1;          // 15
        const int rb = t2 & 1, wb = rb ^ 1; // rb=1, wb=0
        conv3x3_cell<<<dim3(BATCH, HC2 / 8, 7), 128>>>(
            h1buf[wb], HC1, (size_t)HC1 * HW, h2buf[rb], HC2, wt + WOFF_L2, bx2, nullptr, 0,
            HC2, nullptr, 0, Wp2, h2buf[wb], c2, y, t2);
    }
}

// round 13
// speedup vs baseline: 1.1125x; 1.1125x over previous
#include <cuda_runtime.h>
#include <cuda_bf16.h>
#include <math.h>
#include <stdint.h>

// ---------------- problem constants ----------------
#define BATCH 8
#define TSTEPS 16
#define CIN0 192
#define HC0 64
#define HC1 32
#define HC2 64
#define IMG_H 28
#define IMG_W 28
#define HW 784

// ---------------- device scratch (no allocs allowed) ----------------
__device__ float g_gx0[(size_t)BATCH * TSTEPS * 4 * HC0 * HW];

#define SZ0 (BATCH * HC0 * HW)
#define SZ1 (BATCH * HC1 * HW)
#define SZ2 (BATCH * HC2 * HW)
#define OFF_H0A 0
#define OFF_H0B (OFF_H0A + SZ0)
#define OFF_C0  (OFF_H0B + SZ0)
#define OFF_H1A (OFF_C0  + SZ0)
#define OFF_H1B (OFF_H1A + SZ1)
#define OFF_C1  (OFF_H1B + SZ1)
#define OFF_H2A (OFF_C1  + SZ1)
#define OFF_H2B (OFF_H2A + SZ2)
#define OFF_C2  (OFF_H2B + SZ2)
#define NSTATE  (OFF_C2  + SZ2)
__device__ float g_state[NSTATE];

// pre-transposed tf32 weights, 16-cin chunks, ki-major pseudo-taps:
// layout [y][ch16][pt(18)][m(32)][ci(8)], pt = ki*9 + tap,
// oc(m) = (m>>3)*HC + y*8 + (m&7), cin = ch*16 + ki*8 + ci
#define WPC 4608                        // words per 16-chunk (18*32*8)
#define WOFF_GX0 0
#define WSZ_GX0 (8 * 12 * WPC)          // y=8, chunks=12
#define WOFF_L0 (WOFF_GX0 + WSZ_GX0)
#define WSZ_L0  (8 * 4 * WPC)           // y=8, chunks=4
#define WOFF_L1 (WOFF_L0 + WSZ_L0)
#define WSZ_L1  (4 * 6 * WPC)           // y=4, chunks=6
#define WOFF_L2 (WOFF_L1 + WSZ_L1)
#define WSZ_L2  (8 * 6 * WPC)           // y=8, chunks=6
#define WTOTAL  (WOFF_L2 + WSZ_L2)
__device__ uint32_t g_wt[WTOTAL];

__global__ void init_zero_kernel(float* p, int n) {
    int i = blockIdx.x * blockDim.x + threadIdx.x;
    if (i < n) p[i] = 0.f;
}

// ---------------- tf32 / cp.async helpers ----------------
__device__ __forceinline__ uint32_t f2tf32(float f) {
    uint32_t u;
    asm("cvt.rna.tf32.f32 %0, %1;" : "=r"(u) : "f"(f));
    return u;
}

__device__ __forceinline__ void cp_async16(uint32_t saddr, const void* gaddr) {
    asm volatile("cp.async.cg.shared.global [%0], [%1], 16;" :: "r"(saddr), "l"(gaddr));
}
#define CP_ASYNC_COMMIT() asm volatile("cp.async.commit_group;" ::: "memory")
#define CP_ASYNC_WAIT0()  asm volatile("cp.async.wait_group 0;" ::: "memory")

__device__ __forceinline__ void mma_tf32(float c[4],
                                         uint32_t a0, uint32_t a1, uint32_t a2, uint32_t a3,
                                         uint32_t b0, uint32_t b1) {
    asm volatile(
        "mma.sync.aligned.m16n8k8.row.col.f32.tf32.tf32.f32 "
        "{%0,%1,%2,%3}, {%4,%5,%6,%7}, {%8,%9}, {%0,%1,%2,%3};"
        : "+f"(c[0]), "+f"(c[1]), "+f"(c[2]), "+f"(c[3])
        : "r"(a0), "r"(a1), "r"(a2), "r"(a3), "r"(b0), "r"(b1));
}

__device__ __forceinline__ float sigmoidf_(float x) {
    return 1.0f / (1.0f + __expf(-x));
}

// ---------------- fused weight prep: all 4 sets in ONE launch ---------------
__device__ __forceinline__ void prep_one(
    const float* __restrict__ WA, int cinA,
    const float* __restrict__ WB, int cinB,
    int HC, int chunks, uint32_t* __restrict__ dst, int idx)
{
    int ci  = idx & 7;
    int m   = (idx >> 3) & 31;
    int pt  = (idx >> 8) % 18;
    int chy = idx / WPC;
    int ch  = chy % chunks;
    int y   = chy / chunks;
    int ki  = pt / 9;
    int tap = pt % 9;
    int oc  = (m >> 3) * HC + y * 8 + (m & 7);
    int cg  = ch * 16 + ki * 8 + ci;
    float w;
    if (cg < cinA) w = WA[((size_t)oc * cinA + cg) * 9 + tap];
    else           w = WB[((size_t)oc * cinB + (cg - cinA)) * 9 + tap];
    dst[idx] = f2tf32(w);
}

__global__ void prep_all(
    const float* __restrict__ Wx0, const float* __restrict__ Wh0,
    const float* __restrict__ Wx1, const float* __restrict__ Wh1,
    const float* __restrict__ Wx2, const float* __restrict__ Wh2,
    uint32_t* __restrict__ wt)
{
    int i = blockIdx.x * blockDim.x + threadIdx.x;
    if (i < WSZ_GX0) {
        prep_one(Wx0, CIN0, nullptr, 0, HC0, 12, wt + WOFF_GX0, i);
        return;
    }
    i -= WSZ_GX0;
    if (i < WSZ_L0) {
        prep_one(Wh0, HC0, nullptr, 0, HC0, 4, wt + WOFF_L0, i);
        return;
    }
    i -= WSZ_L0;
    if (i < WSZ_L1) {
        prep_one(Wx1, HC0, Wh1, HC1, HC1, 6, wt + WOFF_L1, i);
        return;
    }
    i -= WSZ_L1;
    if (i < WSZ_L2) {
        prep_one(Wx2, HC1, Wh2, HC2, HC2, 6, wt + WOFF_L2, i);
    }
}
#define PREP_TOTAL WTOTAL

// ---------------- conv 3x3 + fused LSTM (16-cin chunks) ----------------
// Block: 128 threads, 4 warps (2M x 2N), M=32 (4 gates x 8 hc), N=112 px.
// K loop: 16-cin chunks; 18 pseudo-taps (ki-major) -> accumulation order
// identical to the 8-cin R5 engine. Dynamic smem, double-buffered.
#define SIN_STR 200
#define IN_WORDS  (16 * SIN_STR)     // 3200 per stage
#define SMEM_BYTES ((2 * IN_WORDS + 2 * WPC) * 4)   // 62464 B

__device__ __forceinline__ void conv_cell_body(
    uint32_t* smem,
    int n, int yb, int rowbase,
    const float* __restrict__ inA, int cinA, size_t inAStride,
    const float* __restrict__ inB, int cinB,
    const uint32_t* __restrict__ wt,
    const float* __restrict__ bias,
    const float* __restrict__ pre, size_t preStride,
    int HC,
    float* __restrict__ out, size_t outStride,   // plain path (hout == nullptr)
    const float* __restrict__ Wp,
    float* __restrict__ hout, float* __restrict__ c,
    float* __restrict__ yout, int t)
{
    uint32_t* s_in[2] = { smem, smem + IN_WORDS };
    uint32_t* s_w[2]  = { smem + 2 * IN_WORDS, smem + 2 * IN_WORDS + WPC };
    float* s_gates    = (float*)smem;            // overlay (used after MMA)

    const int hcb = yb * 8;

    const int tid    = threadIdx.x;
    const int lane   = tid & 31;
    const int wid    = tid >> 5;
    const int warp_m = wid & 1;
    const int warp_n = wid >> 1;
    const int g      = lane >> 2;
    const int ctg    = lane & 3;

    const int chunks = (cinA + cinB) >> 4;

    uint32_t wsm[2];
    wsm[0] = (uint32_t)__cvta_generic_to_shared(s_w[0]);
    wsm[1] = (uint32_t)__cvta_generic_to_shared(s_w[1]);

    int off[7];
#pragma unroll
    for (int s = 0; s < 7; ++s) {
        int nl = warp_n * 56 + s * 8 + g;
        int r = nl / 28;
        off[s] = r * 30 + (nl - r * 28);
    }

    float acc[7][4];
#pragma unroll
    for (int s = 0; s < 7; ++s)
#pragma unroll
        for (int j = 0; j < 4; ++j) acc[s][j] = 0.f;

    float rin[23];

    auto load_chunk = [&](int ch) {
        const int st = ch & 1;
        const int cstart = ch * 16;
        const float* src = (cstart < cinA)
            ? inA + (size_t)n * inAStride + (size_t)cstart * HW
            : inB + ((size_t)n * cinB + (cstart - cinA)) * HW;
#pragma unroll
        for (int k = 0; k < 23; ++k) {
            int idx = tid + k * 128;
            float v = 0.f;
            if (idx < 2880) {
                int ci  = idx / 180;
                int rem = idx - ci * 180;
                int pr  = rem / 30;
                int gr  = rowbase + pr - 1;
                int gc  = (rem - pr * 30) - 1;
                if (gr >= 0 && gr < IMG_H && gc >= 0 && gc < IMG_W)
                    v = src[(size_t)ci * HW + gr * IMG_W + gc];
            }
            rin[k] = v;
        }
        const char* wsrc = (const char*)(wt + ((size_t)yb * chunks + ch) * WPC);
#pragma unroll
        for (int k = 0; k < 9; ++k) {          // 1152 uint4 = 9 * 128
            int i4 = tid + k * 128;
            cp_async16(wsm[st] + i4 * 16, wsrc + (size_t)i4 * 16);
        }
        CP_ASYNC_COMMIT();
    };

    load_chunk(0);

    for (int ch = 0; ch < chunks; ++ch) {
        const int st = ch & 1;
#pragma unroll
        for (int k = 0; k < 23; ++k) {
            int idx = tid + k * 128;
            if (idx < 2880) {
                int ci  = idx / 180;
                int rem = idx - ci * 180;
                s_in[st][ci * SIN_STR + rem] = f2tf32(rin[k]);
            }
        }
        CP_ASYNC_WAIT0();                      // weights for chunk ch landed
        __syncthreads();

        if (ch + 1 < chunks) load_chunk(ch + 1);   // overlaps MMA phase

        const uint32_t* win = s_in[st];
        const uint32_t* ww  = s_w[st];
#pragma unroll
        for (int pt = 0; pt < 18; ++pt) {      // pt = ki*9 + tap (ki-major)
            const int ki  = pt / 9;
            const int tap = pt - ki * 9;
            const int kr  = tap / 3;
            const int kc  = tap - kr * 3;
            const uint32_t* wp = ww + pt * 256 + (warp_m * 16 + g) * 8 + ctg;
            uint32_t a0 = wp[0];
            uint32_t a1 = wp[64];
            uint32_t a2 = wp[4];
            uint32_t a3 = wp[68];
            const int bbase = (ki * 8 + ctg) * SIN_STR + kr * 30 + kc;
#pragma unroll
            for (int s = 0; s < 7; ++s) {
                uint32_t b0 = win[bbase + off[s]];
                uint32_t b1 = win[bbase + off[s] + 4 * SIN_STR];
                mma_tf32(acc[s], a0, a1, a2, a3, b0, b1);
            }
        }
    }

    // ---- epilogue ----
    const int m0  = warp_m * 16 + g;
    const int oc0 = (m0 >> 3) * HC + hcb + (m0 & 7);
    const int m1  = m0 + 8;
    const int oc1 = (m1 >> 3) * HC + hcb + (m1 & 7);
    float bv0 = 0.f, bv1 = 0.f;
    if (bias) { bv0 = bias[oc0]; bv1 = bias[oc1]; }

    if (hout == nullptr) {
#pragma unroll
        for (int s = 0; s < 7; ++s) {
#pragma unroll
            for (int j = 0; j < 2; ++j) {
                int nl = warp_n * 56 + s * 8 + 2 * ctg + j;
                int r = nl / 28;
                int px = (rowbase + r) * IMG_W + (nl - r * 28);
                float v0 = acc[s][j]     + bv0;
                float v1 = acc[s][2 + j] + bv1;
                if (pre) {
                    v0 += pre[(size_t)n * preStride + (size_t)oc0 * HW + px];
                    v1 += pre[(size_t)n * preStride + (size_t)oc1 * HW + px];
                }
                out[(size_t)n * outStride + (size_t)oc0 * HW + px] = v0;
                out[(size_t)n * outStride + (size_t)oc1 * HW + px] = v1;
            }
        }
        return;
    }

    // fused LSTM: exchange gates through smem, then pointwise
    __syncthreads();   // all MMA reads done before overlay overwrite
#pragma unroll
    for (int s = 0; s < 7; ++s) {
#pragma unroll
        for (int j = 0; j < 2; ++j) {
            int nl = warp_n * 56 + s * 8 + 2 * ctg + j;
            float v0 = acc[s][j]     + bv0;
            float v1 = acc[s][2 + j] + bv1;
            if (pre) {
                int r = nl / 28;
                int px = (rowbase + r) * IMG_W + (nl - r * 28);
                v0 += pre[(size_t)n * preStride + (size_t)oc0 * HW + px];
                v1 += pre[(size_t)n * preStride + (size_t)oc1 * HW + px];
            }
            s_gates[((m0 >> 3) * 8 + (m0 & 7)) * 112 + nl] = v0;
            s_gates[((m1 >> 3) * 8 + (m1 & 7)) * 112 + nl] = v1;
        }
    }
    __syncthreads();

#pragma unroll
    for (int k = 0; k < 7; ++k) {
        int e   = tid + k * 128;
        int hcl = e / 112;
        int nl  = e - hcl * 112;
        int r   = nl / 28;
        int px  = (rowbase + r) * IMG_W + (nl - r * 28);
        int hc  = hcb + hcl;

        float g0 = s_gates[(0 * 8 + hcl) * 112 + nl];
        float g1 = s_gates[(1 * 8 + hcl) * 112 + nl];
        float g2 = s_gates[(2 * 8 + hcl) * 112 + nl];
        float g3 = s_gates[(3 * 8 + hcl) * 112 + nl];

        size_t sidx = ((size_t)n * HC + hc) * HW + px;
        float cv = c[sidx];
        float pi = Wp[(size_t)(0 * HC + hc) * HW + px];
        float pf = Wp[(size_t)(1 * HC + hc) * HW + px];
        float po = Wp[(size_t)(2 * HC + hc) * HW + px];

        float gi = sigmoidf_(g0 + cv * pi);
        float gf = sigmoidf_(g1 + cv * pf);
        float cc = gf * cv + gi * tanhf(g2);
        float go = sigmoidf_(g3 + cc * po);
        float hv = go * tanhf(cc);

        c[sidx] = cc;
        hout[sidx] = hv;
        if (yout)
            yout[(((size_t)n * TSTEPS + t) * HC + hc) * HW + px] = hv;
    }
}

__global__ void __launch_bounds__(128) conv3x3_cell(
    const float* __restrict__ inA, int cinA, size_t inAStride,
    const float* __restrict__ inB, int cinB,
    const uint32_t* __restrict__ wt,
    const float* __restrict__ bias,
    const float* __restrict__ pre, size_t preStride,
    int HC,
    float* __restrict__ out, size_t outStride,
    const float* __restrict__ Wp,
    float* __restrict__ hout, float* __restrict__ c,
    float* __restrict__ yout, int t)
{
    extern __shared__ uint32_t smem[];
    conv_cell_body(smem, blockIdx.x, blockIdx.y, blockIdx.z * 4,
                   inA, cinA, inAStride, inB, cinB, wt, bias, pre, preStride,
                   HC, out, outStride, Wp, hout, c, yout, t);
}

// ---------------- host launch (R5 sequential structure) ----------------
extern "C" void kernel_launch(void* const* d_in, const int* in_sizes, int n_in,
                              void* d_out, int out_size)
{
    const float* x   = (const float*)d_in[0];
    const float* Wx0 = (const float*)d_in[1];
    const float* bx0 = (const float*)d_in[2];
    const float* Wh0 = (const float*)d_in[3];
    const float* Wp0 = (const float*)d_in[4];
    const float* Wx1 = (const float*)d_in[5];
    const float* bx1 = (const float*)d_in[6];
    const float* Wh1 = (const float*)d_in[7];
    const float* Wp1 = (const float*)d_in[8];
    const float* Wx2 = (const float*)d_in[9];
    const float* bx2 = (const float*)d_in[10];
    const float* Wh2 = (const float*)d_in[11];
    const float* Wp2 = (const float*)d_in[12];
    float* y = (float*)d_out;

    float *gx0, *state;
    uint32_t* wt;
    cudaGetSymbolAddress((void**)&gx0,   g_gx0);
    cudaGetSymbolAddress((void**)&state, g_state);
    cudaGetSymbolAddress((void**)&wt,    g_wt);

    cudaFuncSetAttribute(conv3x3_cell,
                         cudaFuncAttributeMaxDynamicSharedMemorySize, SMEM_BYTES);

    float* h0buf[2] = { state + OFF_H0A, state + OFF_H0B };
    float* h1buf[2] = { state + OFF_H1A, state + OFF_H1B };
    float* h2buf[2] = { state + OFF_H2A, state + OFF_H2B };
    float* c0 = state + OFF_C0;
    float* c1 = state + OFF_C1;
    float* c2 = state + OFF_C2;

    // launch #1: zero state
    init_zero_kernel<<<(NSTATE + 255) / 256, 256>>>(state, NSTATE);
    // launch #2: all weight prep fused
    prep_all<<<(PREP_TOTAL + 255) / 256, 256>>>(Wx0, Wh0, Wx1, Wh1, Wx2, Wh2, wt);

    // launch #3: batched gx0 = conv(x, Wx0) + bx0 over all B*T frames
    conv3x3_cell<<<dim3(BATCH * TSTEPS, HC0 / 8, 7), 128, SMEM_BYTES>>>(
        x, CIN0, (size_t)CIN0 * HW, nullptr, 0, wt + WOFF_GX0, bx0, nullptr, 0,
        HC0, gx0, (size_t)4 * HC0 * HW, nullptr, nullptr, nullptr, nullptr, 0);

    const size_t gx0FrameStride = (size_t)4 * HC0 * HW;
    const size_t gx0BatchStride = (size_t)TSTEPS * 4 * HC0 * HW;

    for (int t = 0; t < TSTEPS; ++t) {
        const int rb = t & 1;
        const int wb = rb ^ 1;
        float* h0r = h0buf[rb]; float* h0w = h0buf[wb];
        float* h1r = h1buf[rb]; float* h1w = h1buf[wb];
        float* h2r = h2buf[rb]; float* h2w = h2buf[wb];

        // layer 0 (launch #4 at t=0 -> ncu capture slot)
        conv3x3_cell<<<dim3(BATCH, HC0 / 8, 7), 128, SMEM_BYTES>>>(
            h0r, HC0, (size_t)HC0 * HW, nullptr, 0, wt + WOFF_L0, nullptr,
            gx0 + (size_t)t * gx0FrameStride, gx0BatchStride,
            HC0, nullptr, 0, Wp0, h0w, c0, nullptr, t);

        // layer 1
        conv3x3_cell<<<dim3(BATCH, HC1 / 8, 7), 128, SMEM_BYTES>>>(
            h0w, HC0, (size_t)HC0 * HW, h1r, HC1, wt + WOFF_L1, bx1, nullptr, 0,
            HC1, nullptr, 0, Wp1, h1w, c1, nullptr, t);

        // layer 2 (emits y)
        conv3x3_cell<<<dim3(BATCH, HC2 / 8, 7), 128, SMEM_BYTES>>>(
            h1w, HC1, (size_t)HC1 * HW, h2r, HC2, wt + WOFF_L2, bx2, nullptr, 0,
            HC2, nullptr, 0, Wp2, h2w, c2, y, t);
    }
}

// round 14
// speedup vs baseline: 1.1162x; 1.0033x over previous
#include <cuda_runtime.h>
#include <cuda_bf16.h>
#include <math.h>
#include <stdint.h>

// ---------------- problem constants ----------------
#define BATCH 8
#define TSTEPS 16
#define CIN0 192
#define HC0 64
#define HC1 32
#define HC2 64
#define IMG_H 28
#define IMG_W 28
#define HW 784

// ---------------- device scratch (no allocs allowed) ----------------
__device__ float g_gx0[(size_t)BATCH * TSTEPS * 4 * HC0 * HW];

#define SZ0 (BATCH * HC0 * HW)
#define SZ1 (BATCH * HC1 * HW)
#define SZ2 (BATCH * HC2 * HW)
#define OFF_H0A 0
#define OFF_H0B (OFF_H0A + SZ0)
#define OFF_C0  (OFF_H0B + SZ0)
#define OFF_H1A (OFF_C0  + SZ0)
#define OFF_H1B (OFF_H1A + SZ1)
#define OFF_C1  (OFF_H1B + SZ1)
#define OFF_H2A (OFF_C1  + SZ1)
#define OFF_H2B (OFF_H2A + SZ2)
#define OFF_C2  (OFF_H2B + SZ2)
#define NSTATE  (OFF_C2  + SZ2)
__device__ float g_state[NSTATE];

// pre-transposed tf32 weights, 16-cin chunks, ki-major pseudo-taps:
// layout [y][ch16][pt(18)][m(32)][ci(8)], pt = ki*9 + tap,
// oc(m) = (m>>3)*HC + y*8 + (m&7), cin = ch*16 + ki*8 + ci
#define WPC 4608                        // words per 16-chunk (18*32*8)
#define WOFF_GX0 0
#define WSZ_GX0 (8 * 12 * WPC)          // y=8, chunks=12
#define WOFF_L0 (WOFF_GX0 + WSZ_GX0)
#define WSZ_L0  (8 * 4 * WPC)           // y=8, chunks=4
#define WOFF_L1 (WOFF_L0 + WSZ_L0)
#define WSZ_L1  (4 * 6 * WPC)           // y=4, chunks=6
#define WOFF_L2 (WOFF_L1 + WSZ_L1)
#define WSZ_L2  (8 * 6 * WPC)           // y=8, chunks=6
#define WTOTAL  (WOFF_L2 + WSZ_L2)
__device__ uint32_t g_wt[WTOTAL];

__global__ void init_zero_kernel(float* p, int n) {
    int i = blockIdx.x * blockDim.x + threadIdx.x;
    if (i < n) p[i] = 0.f;
}

// ---------------- tf32 / cp.async helpers ----------------
__device__ __forceinline__ uint32_t f2tf32(float f) {
    uint32_t u;
    asm("cvt.rna.tf32.f32 %0, %1;" : "=r"(u) : "f"(f));
    return u;
}

__device__ __forceinline__ void cp_async16(uint32_t saddr, const void* gaddr) {
    asm volatile("cp.async.cg.shared.global [%0], [%1], 16;" :: "r"(saddr), "l"(gaddr));
}
#define CP_ASYNC_COMMIT() asm volatile("cp.async.commit_group;" ::: "memory")
#define CP_ASYNC_WAIT0()  asm volatile("cp.async.wait_group 0;" ::: "memory")

__device__ __forceinline__ void mma_tf32(float c[4],
                                         uint32_t a0, uint32_t a1, uint32_t a2, uint32_t a3,
                                         uint32_t b0, uint32_t b1) {
    asm volatile(
        "mma.sync.aligned.m16n8k8.row.col.f32.tf32.tf32.f32 "
        "{%0,%1,%2,%3}, {%4,%5,%6,%7}, {%8,%9}, {%0,%1,%2,%3};"
        : "+f"(c[0]), "+f"(c[1]), "+f"(c[2]), "+f"(c[3])
        : "r"(a0), "r"(a1), "r"(a2), "r"(a3), "r"(b0), "r"(b1));
}

__device__ __forceinline__ float sigmoidf_(float x) {
    return 1.0f / (1.0f + __expf(-x));
}

// ---------------- fused weight prep: all 4 sets in ONE launch ---------------
__device__ __forceinline__ void prep_one(
    const float* __restrict__ WA, int cinA,
    const float* __restrict__ WB, int cinB,
    int HC, int chunks, uint32_t* __restrict__ dst, int idx)
{
    int ci  = idx & 7;
    int m   = (idx >> 3) & 31;
    int pt  = (idx >> 8) % 18;
    int chy = idx / WPC;
    int ch  = chy % chunks;
    int y   = chy / chunks;
    int ki  = pt / 9;
    int tap = pt % 9;
    int oc  = (m >> 3) * HC + y * 8 + (m & 7);
    int cg  = ch * 16 + ki * 8 + ci;
    float w;
    if (cg < cinA) w = WA[((size_t)oc * cinA + cg) * 9 + tap];
    else           w = WB[((size_t)oc * cinB + (cg - cinA)) * 9 + tap];
    dst[idx] = f2tf32(w);
}

__global__ void prep_all(
    const float* __restrict__ Wx0, const float* __restrict__ Wh0,
    const float* __restrict__ Wx1, const float* __restrict__ Wh1,
    const float* __restrict__ Wx2, const float* __restrict__ Wh2,
    uint32_t* __restrict__ wt)
{
    int i = blockIdx.x * blockDim.x + threadIdx.x;
    if (i < WSZ_GX0) {
        prep_one(Wx0, CIN0, nullptr, 0, HC0, 12, wt + WOFF_GX0, i);
        return;
    }
    i -= WSZ_GX0;
    if (i < WSZ_L0) {
        prep_one(Wh0, HC0, nullptr, 0, HC0, 4, wt + WOFF_L0, i);
        return;
    }
    i -= WSZ_L0;
    if (i < WSZ_L1) {
        prep_one(Wx1, HC0, Wh1, HC1, HC1, 6, wt + WOFF_L1, i);
        return;
    }
    i -= WSZ_L1;
    if (i < WSZ_L2) {
        prep_one(Wx2, HC1, Wh2, HC2, HC2, 6, wt + WOFF_L2, i);
    }
}
#define PREP_TOTAL WTOTAL

// ---------------- conv 3x3 + fused LSTM (16-cin chunks) ----------------
// Block: 128 threads, 4 warps (2M x 2N), M=32 (4 gates x 8 hc), N=112 px.
// K loop: 16-cin chunks; 18 pseudo-taps (ki-major) -> accumulation order
// identical to the 8-cin R5 engine. Dynamic smem, double-buffered.
// __launch_bounds__(128, 3): reg cap 170, guarantees 3 blocks/SM with 62.5KB smem.
#define SIN_STR 200
#define IN_WORDS  (16 * SIN_STR)     // 3200 per stage
#define SMEM_BYTES ((2 * IN_WORDS + 2 * WPC) * 4)   // 62464 B

__device__ __forceinline__ void conv_cell_body(
    uint32_t* smem,
    int n, int yb, int rowbase,
    const float* __restrict__ inA, int cinA, size_t inAStride,
    const float* __restrict__ inB, int cinB,
    const uint32_t* __restrict__ wt,
    const float* __restrict__ bias,
    const float* __restrict__ pre, size_t preStride,
    int HC,
    float* __restrict__ out, size_t outStride,   // plain path (hout == nullptr)
    const float* __restrict__ Wp,
    float* __restrict__ hout, float* __restrict__ c,
    float* __restrict__ yout, int t)
{
    uint32_t* s_in[2] = { smem, smem + IN_WORDS };
    uint32_t* s_w[2]  = { smem + 2 * IN_WORDS, smem + 2 * IN_WORDS + WPC };
    float* s_gates    = (float*)smem;            // overlay (used after MMA)

    const int hcb = yb * 8;

    const int tid    = threadIdx.x;
    const int lane   = tid & 31;
    const int wid    = tid >> 5;
    const int warp_m = wid & 1;
    const int warp_n = wid >> 1;
    const int g      = lane >> 2;
    const int ctg    = lane & 3;

    const int chunks = (cinA + cinB) >> 4;

    uint32_t wsm[2];
    wsm[0] = (uint32_t)__cvta_generic_to_shared(s_w[0]);
    wsm[1] = (uint32_t)__cvta_generic_to_shared(s_w[1]);

    int off[7];
#pragma unroll
    for (int s = 0; s < 7; ++s) {
        int nl = warp_n * 56 + s * 8 + g;
        int r = nl / 28;
        off[s] = r * 30 + (nl - r * 28);
    }

    float acc[7][4];
#pragma unroll
    for (int s = 0; s < 7; ++s)
#pragma unroll
        for (int j = 0; j < 4; ++j) acc[s][j] = 0.f;

    float rin[23];

    auto load_chunk = [&](int ch) {
        const int st = ch & 1;
        const int cstart = ch * 16;
        const float* src = (cstart < cinA)
            ? inA + (size_t)n * inAStride + (size_t)cstart * HW
            : inB + ((size_t)n * cinB + (cstart - cinA)) * HW;
#pragma unroll
        for (int k = 0; k < 23; ++k) {
            int idx = tid + k * 128;
            float v = 0.f;
            if (idx < 2880) {
                int ci  = idx / 180;
                int rem = idx - ci * 180;
                int pr  = rem / 30;
                int gr  = rowbase + pr - 1;
                int gc  = (rem - pr * 30) - 1;
                if (gr >= 0 && gr < IMG_H && gc >= 0 && gc < IMG_W)
                    v = src[(size_t)ci * HW + gr * IMG_W + gc];
            }
            rin[k] = v;
        }
        const char* wsrc = (const char*)(wt + ((size_t)yb * chunks + ch) * WPC);
#pragma unroll
        for (int k = 0; k < 9; ++k) {          // 1152 uint4 = 9 * 128
            int i4 = tid + k * 128;
            cp_async16(wsm[st] + i4 * 16, wsrc + (size_t)i4 * 16);
        }
        CP_ASYNC_COMMIT();
    };

    load_chunk(0);

    for (int ch = 0; ch < chunks; ++ch) {
        const int st = ch & 1;
#pragma unroll
        for (int k = 0; k < 23; ++k) {
            int idx = tid + k * 128;
            if (idx < 2880) {
                int ci  = idx / 180;
                int rem = idx - ci * 180;
                s_in[st][ci * SIN_STR + rem] = f2tf32(rin[k]);
            }
        }
        CP_ASYNC_WAIT0();                      // weights for chunk ch landed
        __syncthreads();

        if (ch + 1 < chunks) load_chunk(ch + 1);   // overlaps MMA phase

        const uint32_t* win = s_in[st];
        const uint32_t* ww  = s_w[st];
#pragma unroll
        for (int pt = 0; pt < 18; ++pt) {      // pt = ki*9 + tap (ki-major)
            const int ki  = pt / 9;
            const int tap = pt - ki * 9;
            const int kr  = tap / 3;
            const int kc  = tap - kr * 3;
            const uint32_t* wp = ww + pt * 256 + (warp_m * 16 + g) * 8 + ctg;
            uint32_t a0 = wp[0];
            uint32_t a1 = wp[64];
            uint32_t a2 = wp[4];
            uint32_t a3 = wp[68];
            const int bbase = (ki * 8 + ctg) * SIN_STR + kr * 30 + kc;
#pragma unroll
            for (int s = 0; s < 7; ++s) {
                uint32_t b0 = win[bbase + off[s]];
                uint32_t b1 = win[bbase + off[s] + 4 * SIN_STR];
                mma_tf32(acc[s], a0, a1, a2, a3, b0, b1);
            }
        }
    }

    // ---- epilogue ----
    const int m0  = warp_m * 16 + g;
    const int oc0 = (m0 >> 3) * HC + hcb + (m0 & 7);
    const int m1  = m0 + 8;
    const int oc1 = (m1 >> 3) * HC + hcb + (m1 & 7);
    float bv0 = 0.f, bv1 = 0.f;
    if (bias) { bv0 = bias[oc0]; bv1 = bias[oc1]; }

    if (hout == nullptr) {
#pragma unroll
        for (int s = 0; s < 7; ++s) {
#pragma unroll
            for (int j = 0; j < 2; ++j) {
                int nl = warp_n * 56 + s * 8 + 2 * ctg + j;
                int r = nl / 28;
                int px = (rowbase + r) * IMG_W + (nl - r * 28);
                float v0 = acc[s][j]     + bv0;
                float v1 = acc[s][2 + j] + bv1;
                if (pre) {
                    v0 += pre[(size_t)n * preStride + (size_t)oc0 * HW + px];
                    v1 += pre[(size_t)n * preStride + (size_t)oc1 * HW + px];
                }
                out[(size_t)n * outStride + (size_t)oc0 * HW + px] = v0;
                out[(size_t)n * outStride + (size_t)oc1 * HW + px] = v1;
            }
        }
        return;
    }

    // fused LSTM: exchange gates through smem, then pointwise
    __syncthreads();   // all MMA reads done before overlay overwrite
#pragma unroll
    for (int s = 0; s < 7; ++s) {
#pragma unroll
        for (int j = 0; j < 2; ++j) {
            int nl = warp_n * 56 + s * 8 + 2 * ctg + j;
            float v0 = acc[s][j]     + bv0;
            float v1 = acc[s][2 + j] + bv1;
            if (pre) {
                int r = nl / 28;
                int px = (rowbase + r) * IMG_W + (nl - r * 28);
                v0 += pre[(size_t)n * preStride + (size_t)oc0 * HW + px];
                v1 += pre[(size_t)n * preStride + (size_t)oc1 * HW + px];
            }
            s_gates[((m0 >> 3) * 8 + (m0 & 7)) * 112 + nl] = v0;
            s_gates[((m1 >> 3) * 8 + (m1 & 7)) * 112 + nl] = v1;
        }
    }
    __syncthreads();

#pragma unroll
    for (int k = 0; k < 7; ++k) {
        int e   = tid + k * 128;
        int hcl = e / 112;
        int nl  = e - hcl * 112;
        int r   = nl / 28;
        int px  = (rowbase + r) * IMG_W + (nl - r * 28);
        int hc  = hcb + hcl;

        float g0 = s_gates[(0 * 8 + hcl) * 112 + nl];
        float g1 = s_gates[(1 * 8 + hcl) * 112 + nl];
        float g2 = s_gates[(2 * 8 + hcl) * 112 + nl];
        float g3 = s_gates[(3 * 8 + hcl) * 112 + nl];

        size_t sidx = ((size_t)n * HC + hc) * HW + px;
        float cv = c[sidx];
        float pi = Wp[(size_t)(0 * HC + hc) * HW + px];
        float pf = Wp[(size_t)(1 * HC + hc) * HW + px];
        float po = Wp[(size_t)(2 * HC + hc) * HW + px];

        float gi = sigmoidf_(g0 + cv * pi);
        float gf = sigmoidf_(g1 + cv * pf);
        float cc = gf * cv + gi * tanhf(g2);
        float go = sigmoidf_(g3 + cc * po);
        float hv = go * tanhf(cc);

        c[sidx] = cc;
        hout[sidx] = hv;
        if (yout)
            yout[(((size_t)n * TSTEPS + t) * HC + hc) * HW + px] = hv;
    }
}

__global__ void __launch_bounds__(128, 3) conv3x3_cell(
    const float* __restrict__ inA, int cinA, size_t inAStride,
    const float* __restrict__ inB, int cinB,
    const uint32_t* __restrict__ wt,
    const float* __restrict__ bias,
    const float* __restrict__ pre, size_t preStride,
    int HC,
    float* __restrict__ out, size_t outStride,
    const float* __restrict__ Wp,
    float* __restrict__ hout, float* __restrict__ c,
    float* __restrict__ yout, int t)
{
    extern __shared__ uint32_t smem[];
    conv_cell_body(smem, blockIdx.x, blockIdx.y, blockIdx.z * 4,
                   inA, cinA, inAStride, inB, cinB, wt, bias, pre, preStride,
                   HC, out, outStride, Wp, hout, c, yout, t);
}

// ---------------- host launch (R5 sequential structure) ----------------
extern "C" void kernel_launch(void* const* d_in, const int* in_sizes, int n_in,
                              void* d_out, int out_size)
{
    const float* x   = (const float*)d_in[0];
    const float* Wx0 = (const float*)d_in[1];
    const float* bx0 = (const float*)d_in[2];
    const float* Wh0 = (const float*)d_in[3];
    const float* Wp0 = (const float*)d_in[4];
    const float* Wx1 = (const float*)d_in[5];
    const float* bx1 = (const float*)d_in[6];
    const float* Wh1 = (const float*)d_in[7];
    const float* Wp1 = (const float*)d_in[8];
    const float* Wx2 = (const float*)d_in[9];
    const float* bx2 = (const float*)d_in[10];
    const float* Wh2 = (const float*)d_in[11];
    const float* Wp2 = (const float*)d_in[12];
    float* y = (float*)d_out;

    float *gx0, *state;
    uint32_t* wt;
    cudaGetSymbolAddress((void**)&gx0,   g_gx0);
    cudaGetSymbolAddress((void**)&state, g_state);
    cudaGetSymbolAddress((void**)&wt,    g_wt);

    cudaFuncSetAttribute(conv3x3_cell,
                         cudaFuncAttributeMaxDynamicSharedMemorySize, SMEM_BYTES);

    float* h0buf[2] = { state + OFF_H0A, state + OFF_H0B };
    float* h1buf[2] = { state + OFF_H1A, state + OFF_H1B };
    float* h2buf[2] = { state + OFF_H2A, state + OFF_H2B };
    float* c0 = state + OFF_C0;
    float* c1 = state + OFF_C1;
    float* c2 = state + OFF_C2;

    // launch #1: zero state
    init_zero_kernel<<<(NSTATE + 255) / 256, 256>>>(state, NSTATE);
    // launch #2: all weight prep fused
    prep_all<<<(PREP_TOTAL + 255) / 256, 256>>>(Wx0, Wh0, Wx1, Wh1, Wx2, Wh2, wt);

    // launch #3: batched gx0 = conv(x, Wx0) + bx0 over all B*T frames
    conv3x3_cell<<<dim3(BATCH * TSTEPS, HC0 / 8, 7), 128, SMEM_BYTES>>>(
        x, CIN0, (size_t)CIN0 * HW, nullptr, 0, wt + WOFF_GX0, bx0, nullptr, 0,
        HC0, gx0, (size_t)4 * HC0 * HW, nullptr, nullptr, nullptr, nullptr, 0);

    const size_t gx0FrameStride = (size_t)4 * HC0 * HW;
    const size_t gx0BatchStride = (size_t)TSTEPS * 4 * HC0 * HW;

    for (int t = 0; t < TSTEPS; ++t) {
        const int rb = t & 1;
        const int wb = rb ^ 1;
        float* h0r = h0buf[rb]; float* h0w = h0buf[wb];
        float* h1r = h1buf[rb]; float* h1w = h1buf[wb];
        float* h2r = h2buf[rb]; float* h2w = h2buf[wb];

        // layer 0 (launch #4 at t=0 -> ncu capture slot)
        conv3x3_cell<<<dim3(BATCH, HC0 / 8, 7), 128, SMEM_BYTES>>>(
            h0r, HC0, (size_t)HC0 * HW, nullptr, 0, wt + WOFF_L0, nullptr,
            gx0 + (size_t)t * gx0FrameStride, gx0BatchStride,
            HC0, nullptr, 0, Wp0, h0w, c0, nullptr, t);

        // layer 1
        conv3x3_cell<<<dim3(BATCH, HC1 / 8, 7), 128, SMEM_BYTES>>>(
            h0w, HC0, (size_t)HC0 * HW, h1r, HC1, wt + WOFF_L1, bx1, nullptr, 0,
            HC1, nullptr, 0, Wp1, h1w, c1, nullptr, t);

        // layer 2 (emits y)
        conv3x3_cell<<<dim3(BATCH, HC2 / 8, 7), 128, SMEM_BYTES>>>(
            h1w, HC1, (size_t)HC1 * HW, h2r, HC2, wt + WOFF_L2, bx2, nullptr, 0,
            HC2, nullptr, 0, Wp2, h2w, c2, y, t);
    }
}

// round 15
// speedup vs baseline: 1.3860x; 1.2417x over previous
#include <cuda_runtime.h>
#include <cuda_bf16.h>
#include <math.h>
#include <stdint.h>

// ---------------- problem constants ----------------
#define BATCH 8
#define TSTEPS 16
#define CIN0 192
#define HC0 64
#define HC1 32
#define HC2 64
#define IMG_H 28
#define IMG_W 28
#define HW 784

// ---------------- device scratch (no allocs allowed) ----------------
__device__ float g_gx0[(size_t)BATCH * TSTEPS * 4 * HC0 * HW];

#define SZ0 (BATCH * HC0 * HW)
#define SZ1 (BATCH * HC1 * HW)
#define SZ2 (BATCH * HC2 * HW)
#define OFF_H0A 0
#define OFF_H0B (OFF_H0A + SZ0)
#define OFF_C0  (OFF_H0B + SZ0)
#define OFF_H1A (OFF_C0  + SZ0)
#define OFF_H1B (OFF_H1A + SZ1)
#define OFF_C1  (OFF_H1B + SZ1)
#define OFF_H2A (OFF_C1  + SZ1)
#define OFF_H2B (OFF_H2A + SZ2)
#define OFF_C2  (OFF_H2B + SZ2)
#define NSTATE  (OFF_C2  + SZ2)
__device__ float g_state[NSTATE];

// pre-transposed tf32 weight buffers, layout [y][chunk][tap][m(32)][ci(8)]
// oc(m) = (m>>3)*HC + y*8 + (m&7)          (R5 layout)
#define WPC 2304
#define WOFF_GX0 0
#define WSZ_GX0 (8 * 24 * WPC)
#define WOFF_L0 (WOFF_GX0 + WSZ_GX0)
#define WSZ_L0  (8 * 8 * WPC)
#define WOFF_L1 (WOFF_L0 + WSZ_L0)
#define WSZ_L1  (4 * 12 * WPC)
#define WOFF_L2 (WOFF_L1 + WSZ_L1)
#define WSZ_L2  (8 * 12 * WPC)
#define WTOTAL  (WOFF_L2 + WSZ_L2)
__device__ uint32_t g_wt[WTOTAL];

__global__ void init_zero_kernel(float* p, int n) {
    int i = blockIdx.x * blockDim.x + threadIdx.x;
    if (i < n) p[i] = 0.f;
}

// ---------------- tf32 / cp.async helpers ----------------
__device__ __forceinline__ uint32_t f2tf32(float f) {
    uint32_t u;
    asm("cvt.rna.tf32.f32 %0, %1;" : "=r"(u) : "f"(f));
    return u;
}

__device__ __forceinline__ void cp_async16(uint32_t saddr, const void* gaddr) {
    asm volatile("cp.async.cg.shared.global [%0], [%1], 16;" :: "r"(saddr), "l"(gaddr));
}
#define CP_ASYNC_COMMIT() asm volatile("cp.async.commit_group;" ::: "memory")
#define CP_ASYNC_WAIT0()  asm volatile("cp.async.wait_group 0;" ::: "memory")

__device__ __forceinline__ void mma_tf32(float c[4],
                                         uint32_t a0, uint32_t a1, uint32_t a2, uint32_t a3,
                                         uint32_t b0, uint32_t b1) {
    asm volatile(
        "mma.sync.aligned.m16n8k8.row.col.f32.tf32.tf32.f32 "
        "{%0,%1,%2,%3}, {%4,%5,%6,%7}, {%8,%9}, {%0,%1,%2,%3};"
        : "+f"(c[0]), "+f"(c[1]), "+f"(c[2]), "+f"(c[3])
        : "r"(a0), "r"(a1), "r"(a2), "r"(a3), "r"(b0), "r"(b1));
}

__device__ __forceinline__ float sigmoidf_(float x) {
    return 1.0f / (1.0f + __expf(-x));
}

// ---------------- fused weight prep: all 4 sets in ONE launch ---------------
__device__ __forceinline__ void prep_one(
    const float* __restrict__ WA, int cinA,
    const float* __restrict__ WB, int cinB,
    int HC, int chunks, uint32_t* __restrict__ dst, int idx)
{
    int ci  = idx & 7;
    int m   = (idx >> 3) & 31;
    int tap = (idx >> 8) % 9;
    int chy = idx / WPC;
    int ch  = chy % chunks;
    int y   = chy / chunks;
    int oc  = (m >> 3) * HC + y * 8 + (m & 7);
    int cg  = ch * 8 + ci;
    float w;
    if (cg < cinA) w = WA[((size_t)oc * cinA + cg) * 9 + tap];
    else           w = WB[((size_t)oc * cinB + (cg - cinA)) * 9 + tap];
    dst[idx] = f2tf32(w);
}

__global__ void prep_all(
    const float* __restrict__ Wx0, const float* __restrict__ Wh0,
    const float* __restrict__ Wx1, const float* __restrict__ Wh1,
    const float* __restrict__ Wx2, const float* __restrict__ Wh2,
    uint32_t* __restrict__ wt)
{
    int i = blockIdx.x * blockDim.x + threadIdx.x;
    if (i < WSZ_GX0) { prep_one(Wx0, CIN0, nullptr, 0, HC0, 24, wt + WOFF_GX0, i); return; }
    i -= WSZ_GX0;
    if (i < WSZ_L0)  { prep_one(Wh0, HC0,  nullptr, 0, HC0,  8, wt + WOFF_L0,  i); return; }
    i -= WSZ_L0;
    if (i < WSZ_L1)  { prep_one(Wx1, HC0,  Wh1, HC1, HC1, 12, wt + WOFF_L1,  i); return; }
    i -= WSZ_L1;
    if (i < WSZ_L2)  { prep_one(Wx2, HC1,  Wh2, HC2, HC2, 12, wt + WOFF_L2,  i); }
}
#define PREP_TOTAL WTOTAL

// ---------------- conv 3x3 + fused LSTM (R5 engine + cp.async weights) ------
#define SIN_STR 200

struct SmemU {
    union {
        struct {
            uint32_t in[2][8 * SIN_STR];
            uint32_t w[2][WPC];
        } mm;
        float gates[4 * 8 * 112];
    };
};

__device__ __forceinline__ void conv_cell_body(
    SmemU& sm,
    int n, int yb, int rowbase,
    const float* __restrict__ inA, int cinA, size_t inAStride,
    const float* __restrict__ inB, int cinB,
    const uint32_t* __restrict__ wt,
    const float* __restrict__ bias,
    const float* __restrict__ pre, size_t preStride,
    int HC,
    float* __restrict__ out, size_t outStride,   // plain path (hout == nullptr)
    const float* __restrict__ Wp,
    float* __restrict__ hout, float* __restrict__ c,
    float* __restrict__ yout, int t)
{
    const int hcb = yb * 8;

    const int tid    = threadIdx.x;
    const int lane   = tid & 31;
    const int wid    = tid >> 5;
    const int warp_m = wid & 1;
    const int warp_n = wid >> 1;
    const int g      = lane >> 2;
    const int ctg    = lane & 3;

    const int chunks = (cinA + cinB) >> 3;

    uint32_t wsm[2];
    wsm[0] = (uint32_t)__cvta_generic_to_shared(sm.mm.w[0]);
    wsm[1] = (uint32_t)__cvta_generic_to_shared(sm.mm.w[1]);

    int off[7];
#pragma unroll
    for (int s = 0; s < 7; ++s) {
        int nl = warp_n * 56 + s * 8 + g;
        int r = nl / 28;
        off[s] = r * 30 + (nl - r * 28);
    }

    float acc[7][4];
#pragma unroll
    for (int s = 0; s < 7; ++s)
#pragma unroll
        for (int j = 0; j < 4; ++j) acc[s][j] = 0.f;

    float rin[12];

    auto load_chunk = [&](int ch) {
        const int st = ch & 1;
        const int cstart = ch * 8;
        const float* src = (cstart < cinA)
            ? inA + (size_t)n * inAStride + (size_t)cstart * HW
            : inB + ((size_t)n * cinB + (cstart - cinA)) * HW;
#pragma unroll
        for (int k = 0; k < 12; ++k) {
            int idx = tid + k * 128;
            float v = 0.f;
            if (idx < 1440) {
                int ci  = idx / 180;
                int rem = idx - ci * 180;
                int pr  = rem / 30;
                int gr  = rowbase + pr - 1;
                int gc  = (rem - pr * 30) - 1;
                if (gr >= 0 && gr < IMG_H && gc >= 0 && gc < IMG_W)
                    v = src[(size_t)ci * HW + gr * IMG_W + gc];
            }
            rin[k] = v;
        }
        // weights: straight to smem via cp.async (576 uint4 = 4.5 * 128)
        const char* wsrc = (const char*)(wt + ((size_t)yb * chunks + ch) * WPC);
#pragma unroll
        for (int k = 0; k < 5; ++k) {
            int i4 = tid + k * 128;
            if (i4 < 576) cp_async16(wsm[st] + i4 * 16, wsrc + (size_t)i4 * 16);
        }
        CP_ASYNC_COMMIT();
    };

    load_chunk(0);

    for (int ch = 0; ch < chunks; ++ch) {
        const int st = ch & 1;
#pragma unroll
        for (int k = 0; k < 12; ++k) {
            int idx = tid + k * 128;
            if (idx < 1440) {
                int ci  = idx / 180;
                int rem = idx - ci * 180;
                sm.mm.in[st][ci * SIN_STR + rem] = f2tf32(rin[k]);
            }
        }
        CP_ASYNC_WAIT0();          // weights for chunk ch landed
        __syncthreads();

        if (ch + 1 < chunks) load_chunk(ch + 1);   // overlaps MMA phase

        const uint32_t* win = sm.mm.in[st];
        const uint32_t* ww  = sm.mm.w[st];
#pragma unroll
        for (int kr = 0; kr < 3; ++kr) {
#pragma unroll
            for (int kc = 0; kc < 3; ++kc) {
                const int tap = kr * 3 + kc;
                const uint32_t* wp = ww + tap * 256 + (warp_m * 16 + g) * 8 + ctg;
                uint32_t a0 = wp[0];
                uint32_t a1 = wp[64];
                uint32_t a2 = wp[4];
                uint32_t a3 = wp[68];
                const int bbase = ctg * SIN_STR + kr * 30 + kc;
#pragma unroll
                for (int s = 0; s < 7; ++s) {
                    uint32_t b0 = win[bbase + off[s]];
                    uint32_t b1 = win[bbase + off[s] + 4 * SIN_STR];
                    mma_tf32(acc[s], a0, a1, a2, a3, b0, b1);
                }
            }
        }
    }

    // ---- epilogue ----
    const int m0  = warp_m * 16 + g;
    const int oc0 = (m0 >> 3) * HC + hcb + (m0 & 7);
    const int m1  = m0 + 8;
    const int oc1 = (m1 >> 3) * HC + hcb + (m1 & 7);
    float bv0 = 0.f, bv1 = 0.f;
    if (bias) { bv0 = bias[oc0]; bv1 = bias[oc1]; }

    if (hout == nullptr) {
#pragma unroll
        for (int s = 0; s < 7; ++s) {
#pragma unroll
            for (int j = 0; j < 2; ++j) {
                int nl = warp_n * 56 + s * 8 + 2 * ctg + j;
                int r = nl / 28;
                int px = (rowbase + r) * IMG_W + (nl - r * 28);
                float v0 = acc[s][j]     + bv0;
                float v1 = acc[s][2 + j] + bv1;
                if (pre) {
                    v0 += pre[(size_t)n * preStride + (size_t)oc0 * HW + px];
                    v1 += pre[(size_t)n * preStride + (size_t)oc1 * HW + px];
                }
                out[(size_t)n * outStride + (size_t)oc0 * HW + px] = v0;
                out[(size_t)n * outStride + (size_t)oc1 * HW + px] = v1;
            }
        }
        return;
    }

    // fused LSTM: exchange gates through smem, then pointwise
    __syncthreads();   // all MMA reads done before union overwrite
#pragma unroll
    for (int s = 0; s < 7; ++s) {
#pragma unroll
        for (int j = 0; j < 2; ++j) {
            int nl = warp_n * 56 + s * 8 + 2 * ctg + j;
            float v0 = acc[s][j]     + bv0;
            float v1 = acc[s][2 + j] + bv1;
            if (pre) {
                int r = nl / 28;
                int px = (rowbase + r) * IMG_W + (nl - r * 28);
                v0 += pre[(size_t)n * preStride + (size_t)oc0 * HW + px];
                v1 += pre[(size_t)n * preStride + (size_t)oc1 * HW + px];
            }
            sm.gates[((m0 >> 3) * 8 + (m0 & 7)) * 112 + nl] = v0;
            sm.gates[((m1 >> 3) * 8 + (m1 & 7)) * 112 + nl] = v1;
        }
    }
    __syncthreads();

#pragma unroll
    for (int k = 0; k < 7; ++k) {
        int e   = tid + k * 128;
        int hcl = e / 112;
        int nl  = e - hcl * 112;
        int r   = nl / 28;
        int px  = (rowbase + r) * IMG_W + (nl - r * 28);
        int hc  = hcb + hcl;

        float g0 = sm.gates[(0 * 8 + hcl) * 112 + nl];
        float g1 = sm.gates[(1 * 8 + hcl) * 112 + nl];
        float g2 = sm.gates[(2 * 8 + hcl) * 112 + nl];
        float g3 = sm.gates[(3 * 8 + hcl) * 112 + nl];

        size_t sidx = ((size_t)n * HC + hc) * HW + px;
        float cv = c[sidx];
        float pi = Wp[(size_t)(0 * HC + hc) * HW + px];
        float pf = Wp[(size_t)(1 * HC + hc) * HW + px];
        float po = Wp[(size_t)(2 * HC + hc) * HW + px];

        float gi = sigmoidf_(g0 + cv * pi);
        float gf = sigmoidf_(g1 + cv * pf);
        float cc = gf * cv + gi * tanhf(g2);
        float go = sigmoidf_(g3 + cc * po);
        float hv = go * tanhf(cc);

        c[sidx] = cc;
        hout[sidx] = hv;
        if (yout)
            yout[(((size_t)n * TSTEPS + t) * HC + hc) * HW + px] = hv;
    }
}

__global__ void __launch_bounds__(128, 4) conv3x3_cell(
    const float* __restrict__ inA, int cinA, size_t inAStride,
    const float* __restrict__ inB, int cinB,
    const uint32_t* __restrict__ wt,
    const float* __restrict__ bias,
    const float* __restrict__ pre, size_t preStride,
    int HC,
    float* __restrict__ out, size_t outStride,
    const float* __restrict__ Wp,
    float* __restrict__ hout, float* __restrict__ c,
    float* __restrict__ yout, int t)
{
    __shared__ SmemU sm;
    conv_cell_body(sm, blockIdx.x, blockIdx.y, blockIdx.z * 4,
                   inA, cinA, inAStride, inB, cinB, wt, bias, pre, preStride,
                   HC, out, outStride, Wp, hout, c, yout, t);
}

// ---------------- host launch (R5 sequential structure) ----------------
extern "C" void kernel_launch(void* const* d_in, const int* in_sizes, int n_in,
                              void* d_out, int out_size)
{
    const float* x   = (const float*)d_in[0];
    const float* Wx0 = (const float*)d_in[1];
    const float* bx0 = (const float*)d_in[2];
    const float* Wh0 = (const float*)d_in[3];
    const float* Wp0 = (const float*)d_in[4];
    const float* Wx1 = (const float*)d_in[5];
    const float* bx1 = (const float*)d_in[6];
    const float* Wh1 = (const float*)d_in[7];
    const float* Wp1 = (const float*)d_in[8];
    const float* Wx2 = (const float*)d_in[9];
    const float* bx2 = (const float*)d_in[10];
    const float* Wh2 = (const float*)d_in[11];
    const float* Wp2 = (const float*)d_in[12];
    float* y = (float*)d_out;

    float *gx0, *state;
    uint32_t* wt;
    cudaGetSymbolAddress((void**)&gx0,   g_gx0);
    cudaGetSymbolAddress((void**)&state, g_state);
    cudaGetSymbolAddress((void**)&wt,    g_wt);

    float* h0buf[2] = { state + OFF_H0A, state + OFF_H0B };
    float* h1buf[2] = { state + OFF_H1A, state + OFF_H1B };
    float* h2buf[2] = { state + OFF_H2A, state + OFF_H2B };
    float* c0 = state + OFF_C0;
    float* c1 = state + OFF_C1;
    float* c2 = state + OFF_C2;

    init_zero_kernel<<<(NSTATE + 255) / 256, 256>>>(state, NSTATE);
    prep_all<<<(PREP_TOTAL + 255) / 256, 256>>>(Wx0, Wh0, Wx1, Wh1, Wx2, Wh2, wt);

    // batched gx0 = conv(x, Wx0) + bx0 over all B*T frames (plain path)
    conv3x3_cell<<<dim3(BATCH * TSTEPS, HC0 / 8, 7), 128>>>(
        x, CIN0, (size_t)CIN0 * HW, nullptr, 0, wt + WOFF_GX0, bx0, nullptr, 0,
        HC0, gx0, (size_t)4 * HC0 * HW, nullptr, nullptr, nullptr, nullptr, 0);

    const size_t gx0FrameStride = (size_t)4 * HC0 * HW;
    const size_t gx0BatchStride = (size_t)TSTEPS * 4 * HC0 * HW;

    for (int t = 0; t < TSTEPS; ++t) {
        const int rb = t & 1;
        const int wb = rb ^ 1;
        float* h0r = h0buf[rb]; float* h0w = h0buf[wb];
        float* h1r = h1buf[rb]; float* h1w = h1buf[wb];
        float* h2r = h2buf[rb]; float* h2w = h2buf[wb];

        // layer 0: gates = gx0[b,t] + conv(h0_old, Wh0); fused LSTM
        conv3x3_cell<<<dim3(BATCH, HC0 / 8, 7), 128>>>(
            h0r, HC0, (size_t)HC0 * HW, nullptr, 0, wt + WOFF_L0, nullptr,
            gx0 + (size_t)t * gx0FrameStride, gx0BatchStride,
            HC0, nullptr, 0, Wp0, h0w, c0, nullptr, t);

        // layer 1: gates = conv(h0_new, Wx1) + conv(h1_old, Wh1) + bx1
        conv3x3_cell<<<dim3(BATCH, HC1 / 8, 7), 128>>>(
            h0w, HC0, (size_t)HC0 * HW, h1r, HC1, wt + WOFF_L1, bx1, nullptr, 0,
            HC1, nullptr, 0, Wp1, h1w, c1, nullptr, t);

        // layer 2: gates = conv(h1_new, Wx2) + conv(h2_old, Wh2) + bx2; emits y
        conv3x3_cell<<<dim3(BATCH, HC2 / 8, 7), 128>>>(
            h1w, HC1, (size_t)HC1 * HW, h2r, HC2, wt + WOFF_L2, bx2, nullptr, 0,
            HC2, nullptr, 0, Wp2, h2w, c2, y, t);
    }
}